// round 11
// baseline (speedup 1.0000x reference)
#include <cuda_runtime.h>
#include <cuda_fp16.h>
#include <cstdint>

#define NTOK_MAX (8 * 4096)
#define IN_F 1024
#define CUT1 5000
#define CUT2 20000

// B' scratch: last 384 output rows. B0: 1024x512 halves (256 rows),
// B1: 1024x256 halves (128 rows). A' lives IN-PLACE in each token's out row.
#define CUTROW2 (NTOK_MAX - 384)

__device__ int g_cnt4[4];   // {t0_lo, t0_hi, t1_lo, t1_hi}
__device__ int g_l0[NTOK_MAX];
__device__ int g_l1[NTOK_MAX];
__device__ int g_h0[NTOK_MAX];
__device__ int g_h1[NTOK_MAX];

// ---------------------------------------------------------------------------
__global__ void init_k() {
    if (threadIdx.x < 4) g_cnt4[threadIdx.x] = 0;
}

__global__ void classify4_k(const int* __restrict__ tokens, int n) {
    int i = blockIdx.x * blockDim.x + threadIdx.x;
    int t = (i < n) ? tokens[i] : -1;
    int c = (t >= CUT2) ? 1 : ((t >= CUT1) ? 0 : -1);
    int hh = (i >= CUTROW2) ? 1 : 0;
    int lane = threadIdx.x & 31;
#pragma unroll
    for (int cc = 0; cc < 2; ++cc) {
#pragma unroll
        for (int h2 = 0; h2 < 2; ++h2) {
            unsigned m = __ballot_sync(0xffffffffu, c == cc && hh == h2);
            if (c == cc && hh == h2) {
                int leader = __ffs(m) - 1;
                int base = 0;
                if (lane == leader) base = atomicAdd(&g_cnt4[cc * 2 + h2], __popc(m));
                base = __shfl_sync(m, base, leader);
                int slot = base + __popc(m & ((1u << lane) - 1u));
                int* lst = h2 ? (cc ? g_h1 : g_h0) : (cc ? g_l1 : g_l0);
                lst[slot] = i;
            }
        }
    }
}

__global__ void head_lo_k(const int* __restrict__ tokens,
                          const float* __restrict__ head_emb,
                          float* __restrict__ out) {
    int p = blockIdx.x;                      // < CUTROW2 by grid
    int t = __ldg(&tokens[p]);
    if (t >= CUT1) return;
    const float4* src = (const float4*)(head_emb + (size_t)t * IN_F);
    float4* dst = (float4*)(out + (size_t)p * IN_F);
    dst[threadIdx.x]       = src[threadIdx.x];
    dst[threadIdx.x + 128] = src[threadIdx.x + 128];
}

__global__ void head_hi_k(const int* __restrict__ tokens,
                          const float* __restrict__ head_emb,
                          float* __restrict__ out, int n) {
    int p = CUTROW2 + blockIdx.x;
    if (p >= n) return;
    int t = __ldg(&tokens[p]);
    if (t >= CUT1) return;
    const float4* src = (const float4*)(head_emb + (size_t)t * IN_F);
    float4* dst = (float4*)(out + (size_t)p * IN_F);
    dst[threadIdx.x]       = src[threadIdx.x];
    dst[threadIdx.x + 128] = src[threadIdx.x + 128];
}

// ---------------------------------------------------------------------------
__device__ __forceinline__ uint32_t cvt2(float f0, float f1) {
    uint32_t r;
    asm("cvt.rn.f16x2.f32 %0, %1, %2;" : "=r"(r) : "f"(f1), "f"(f0));
    return r;
}

// Gather + convert lo-list embedding rows into fp16 A' IN-PLACE at the start
// of each token's own output row.
template <int K, int LOW, int C>
__global__ void packA_k(const float* __restrict__ emb,
                        const int* __restrict__ tokens,
                        float* __restrict__ out) {
    constexpr int TPR = K / 16;            // threads per row
    constexpr int RPB = 256 / TPR;         // rows per block
    __shared__ int sIdx[RPB];
    const int cnt = g_cnt4[C * 2];
    const int r0 = blockIdx.x * RPB;
    if (r0 >= cnt) return;
    if (threadIdx.x < RPB) {
        int rr = r0 + threadIdx.x;
        sIdx[threadIdx.x] = (rr < cnt) ? (C ? g_l1 : g_l0)[rr] : 0;
    }
    __syncthreads();
    int r = r0 + threadIdx.x / TPR;
    if (r >= cnt) return;
    int pos = sIdx[threadIdx.x / TPR];
    int j = (threadIdx.x % TPR) * 16;
    int tok = __ldg(&tokens[pos]) - LOW;
    const float4* src = (const float4*)(emb + (size_t)tok * K + j);
    float4 v0 = src[0], v1 = src[1], v2 = src[2], v3 = src[3];
    uint4 o0 = make_uint4(cvt2(v0.x, v0.y), cvt2(v0.z, v0.w),
                          cvt2(v1.x, v1.y), cvt2(v1.z, v1.w));
    uint4 o1 = make_uint4(cvt2(v2.x, v2.y), cvt2(v2.z, v2.w),
                          cvt2(v3.x, v3.y), cvt2(v3.z, v3.w));
    __half* dst = (__half*)(out + (size_t)pos * IN_F) + j;
    *(uint4*)dst = o0;
    *(uint4*)(dst + 8) = o1;
}

// Convert BOTH weight matrices into fp16 B' scratch (tail 384 rows of out).
__global__ void packB_k(const float* __restrict__ w0,
                        const float* __restrict__ w1,
                        float* __restrict__ out) {
    __half* B0 = (__half*)(out + (size_t)CUTROW2 * IN_F);
    __half* B1 = B0 + (size_t)1024 * 512;
    int K, r, j;
    const float* w;
    __half* Bp;
    if (blockIdx.x < 128) {                 // B0: K=512, 32 thr/row, 8 rows/blk
        K = 512; w = w0; Bp = B0;
        r = blockIdx.x * 8 + threadIdx.x / 32;
        j = (threadIdx.x % 32) * 16;
    } else {                                // B1: K=256, 16 thr/row, 16 rows/blk
        K = 256; w = w1; Bp = B1;
        r = (blockIdx.x - 128) * 16 + threadIdx.x / 16;
        j = (threadIdx.x % 16) * 16;
    }
    const float4* src = (const float4*)(w + (size_t)r * K + j);
    float4 v0 = src[0], v1 = src[1], v2 = src[2], v3 = src[3];
    uint4 o0 = make_uint4(cvt2(v0.x, v0.y), cvt2(v0.z, v0.w),
                          cvt2(v1.x, v1.y), cvt2(v1.z, v1.w));
    uint4 o1 = make_uint4(cvt2(v2.x, v2.y), cvt2(v2.z, v2.w),
                          cvt2(v3.x, v3.y), cvt2(v3.z, v3.w));
    __half* dst = Bp + (size_t)r * K + j;
    *(uint4*)dst = o0;
    *(uint4*)(dst + 8) = o1;
}

// ---------------------------------------------------------------------------
__device__ __forceinline__ void ldsm_x4(uint32_t& r0, uint32_t& r1,
                                        uint32_t& r2, uint32_t& r3,
                                        const void* smem_ptr) {
    uint32_t addr = (uint32_t)__cvta_generic_to_shared(smem_ptr);
    asm volatile("ldmatrix.sync.aligned.m8n8.x4.shared.b16 {%0,%1,%2,%3}, [%4];"
                 : "=r"(r0), "=r"(r1), "=r"(r2), "=r"(r3) : "r"(addr));
}

__device__ __forceinline__ void mma16816(float* c, const uint32_t* a,
                                         uint32_t b0, uint32_t b1) {
    asm volatile(
        "mma.sync.aligned.m16n8k16.row.col.f32.f16.f16.f32 "
        "{%0,%1,%2,%3}, {%4,%5,%6,%7}, {%8,%9}, {%0,%1,%2,%3};"
        : "+f"(c[0]), "+f"(c[1]), "+f"(c[2]), "+f"(c[3])
        : "r"(a[0]), "r"(a[1]), "r"(a[2]), "r"(a[3]), "r"(b0), "r"(b1));
}

__device__ __forceinline__ void cp16(void* dst_smem, const void* src) {
    uint32_t d = (uint32_t)__cvta_generic_to_shared(dst_smem);
    asm volatile("cp.async.cg.shared.global [%0], [%1], 16;\n" :: "r"(d), "l"(src));
}

// ---------------------------------------------------------------------------
// Persistent-A dense GEMM. Each CTA: 64 lo-list rows, A' (64xK fp16) loaded
// once into smem from the rows' own out-slots, then full N=1024 computed as
// 8 slices of 128, K chunks of 64 halves with a 2-stage cp.async B pipeline.
// Outputs overwrite the A' in-place (safe: A' is in smem by then, and only
// this CTA touches these rows).
template <int K, int C>
__global__ void __launch_bounds__(256, 2)
dense2_k(const __half* __restrict__ Bp, float* __restrict__ out) {
    constexpr int LDA = K + 8;
    constexpr int LDB = 72;
    constexpr int NCK = K / 64;            // 8 or 4
    constexpr int G = 8 * NCK;             // total chunks
    extern __shared__ __half dsm[];
    __half* Asm = dsm;                     // [64][LDA]
    __half* Bsm = dsm + 64 * LDA;          // [2][128][LDB]
    __shared__ int sPos[64];

    const int count = g_cnt4[C * 2];
    const int rowBase = blockIdx.x * 64;
    if (rowBase >= count) return;
    const int rem = min(64, count - rowBase);
    const int tid = threadIdx.x;
    const int lane = tid & 31;
    const int wid = tid >> 5;

    if (tid < 64) sPos[tid] = (C ? g_l1 : g_l0)[rowBase + min(tid, rem - 1)];
    __syncthreads();

    // ---- A load: 4 threads per row, K/32 x 16B units each
    {
        int row = tid >> 2;
        const __half* aRow = (const __half*)(out + (size_t)sPos[row] * IN_F);
#pragma unroll
        for (int q = 0; q < K / 32; q++) {
            int col = ((tid & 3) + q * 4) * 8;
            cp16(&Asm[row * LDA + col], aRow + col);
        }
    }

    // ---- B chunk issue: 2 threads per row, 4 x 16B units each
    const int brow = tid >> 1;
#define BISSUE(g)                                                         \
    do {                                                                  \
        int s0_ = (g) / NCK, kc_ = (g) % NCK, stg_ = (g) & 1;             \
        const __half* bsrc = Bp + (size_t)(s0_ * 128 + brow) * K          \
                             + kc_ * 64;                                  \
        __half* bdst = Bsm + stg_ * (128 * LDB) + brow * LDB;             \
        _Pragma("unroll")                                                 \
        for (int p_ = 0; p_ < 4; p_++) {                                  \
            int col = ((tid & 1) + p_ * 2) * 8;                           \
            cp16(bdst + col, bsrc + col);                                 \
        }                                                                 \
    } while (0)

    BISSUE(0);
    asm volatile("cp.async.commit_group;\n");   // group: A + B(0)

    const int wm = (wid & 1) * 32;
    const int wn = (wid >> 1) * 32;
    float c[2][4][4];
#pragma unroll
    for (int i = 0; i < 2; i++)
#pragma unroll
        for (int j = 0; j < 4; j++)
#pragma unroll
            for (int q = 0; q < 4; q++) c[i][j][q] = 0.f;

    const int aLdRow = lane & 15;
    const int aLdCol = (lane >> 4) * 8;
    const int bLdRow = ((lane >> 4) << 3) + (lane & 7);
    const int bLdCol = lane & 8;

#pragma unroll 1
    for (int g = 0; g < G; g++) {
        asm volatile("cp.async.wait_group 0;\n");
        __syncthreads();
        if (g + 1 < G) {
            BISSUE(g + 1);                  // fills other stage; overlaps MMA
            asm volatile("cp.async.commit_group;\n");
        }
        const int s0 = g / NCK, kc = g % NCK, stg = g & 1;
        const __half* bb = Bsm + stg * (128 * LDB);
#pragma unroll
        for (int kf = 0; kf < 4; kf++) {
            uint32_t AF[2][4], BF[2][4];
#pragma unroll
            for (int mf = 0; mf < 2; mf++)
                ldsm_x4(AF[mf][0], AF[mf][1], AF[mf][2], AF[mf][3],
                        &Asm[(wm + mf * 16 + aLdRow) * LDA
                             + kc * 64 + kf * 16 + aLdCol]);
#pragma unroll
            for (int gg = 0; gg < 2; gg++)
                ldsm_x4(BF[gg][0], BF[gg][1], BF[gg][2], BF[gg][3],
                        bb + (wn + gg * 16 + bLdRow) * LDB + kf * 16 + bLdCol);
#pragma unroll
            for (int mf = 0; mf < 2; mf++)
#pragma unroll
                for (int nf = 0; nf < 4; nf++)
                    mma16816(c[mf][nf], AF[mf],
                             BF[nf >> 1][(nf & 1) * 2], BF[nf >> 1][(nf & 1) * 2 + 1]);
        }

        if (kc == NCK - 1) {
            // slice epilogue: write 64x128 outputs for n0 = s0*128, reset accums
            int n0 = s0 * 128;
#pragma unroll
            for (int mf = 0; mf < 2; mf++) {
#pragma unroll
                for (int nf = 0; nf < 4; nf++) {
                    int r0 = wm + mf * 16 + (lane >> 2);
                    int col = n0 + wn + nf * 8 + 2 * (lane & 3);
                    if (r0 < rem)
                        *(float2*)(out + (size_t)sPos[r0] * IN_F + col) =
                            make_float2(c[mf][nf][0], c[mf][nf][1]);
                    if (r0 + 8 < rem)
                        *(float2*)(out + (size_t)sPos[r0 + 8] * IN_F + col) =
                            make_float2(c[mf][nf][2], c[mf][nf][3]);
#pragma unroll
                    for (int q = 0; q < 4; q++) c[mf][nf][q] = 0.f;
                }
            }
        }
    }
#undef BISSUE
}

// ---------------------------------------------------------------------------
// Fused gather+convert fp16 GEMM for the <=384 hi-list rows. R9-proven
// structure (tile 128x128, double-buffered, 1 sync/chunk). Runs after dense.
template <int K, int LOW, int C>
__global__ void __launch_bounds__(256, 2)
fused_hi_k(const float* __restrict__ emb,
           const float* __restrict__ w,
           const int* __restrict__ tokens,
           float* __restrict__ out) {
    constexpr int TM = 128, TN = 128, LD = 40;
    constexpr int NC = K / 32;
    __shared__ __align__(16) __half sA[2][TM][LD];
    __shared__ __align__(16) __half sB[2][TN][LD];
    __shared__ int sPos[TM];

    const int count = g_cnt4[C * 2 + 1];
    const int rowBase = blockIdx.x * TM;
    if (rowBase >= count) return;
    const int rem = min(TM, count - rowBase);
    const int n0 = blockIdx.y * TN;
    const int tid = threadIdx.x;
    const int lane = tid & 31;
    const int wid = tid >> 5;

    if (tid < TM) sPos[tid] = (C ? g_h1 : g_h0)[rowBase + min(tid, rem - 1)];
    __syncthreads();

    const int ar = tid >> 1;
    const int aseg = (tid & 1) * 16;
    const float* aPtr = emb + (size_t)(__ldg(&tokens[sPos[ar]]) - LOW) * K + aseg;
    const float* bPtr = w + (size_t)(n0 + ar) * K + aseg;

    float ra[16], rb[16];
#define LOADREGS(kc)                                              \
    do {                                                          \
        const float* ap_ = aPtr + (kc) * 32;                      \
        const float* bp_ = bPtr + (kc) * 32;                      \
        _Pragma("unroll")                                         \
        for (int q_ = 0; q_ < 4; q_++) {                          \
            float4 va_ = *(const float4*)(ap_ + q_ * 4);          \
            float4 vb_ = *(const float4*)(bp_ + q_ * 4);          \
            ra[q_*4+0]=va_.x; ra[q_*4+1]=va_.y;                   \
            ra[q_*4+2]=va_.z; ra[q_*4+3]=va_.w;                   \
            rb[q_*4+0]=vb_.x; rb[q_*4+1]=vb_.y;                   \
            rb[q_*4+2]=vb_.z; rb[q_*4+3]=vb_.w;                   \
        }                                                         \
    } while (0)

#define CVTSTS(buf)                                                            \
    do {                                                                       \
        *(uint4*)&sA[buf][ar][aseg] =                                          \
            make_uint4(cvt2(ra[0], ra[1]), cvt2(ra[2], ra[3]),                 \
                       cvt2(ra[4], ra[5]), cvt2(ra[6], ra[7]));                \
        *(uint4*)&sA[buf][ar][aseg + 8] =                                      \
            make_uint4(cvt2(ra[8], ra[9]),  cvt2(ra[10], ra[11]),              \
                       cvt2(ra[12], ra[13]), cvt2(ra[14], ra[15]));            \
        *(uint4*)&sB[buf][ar][aseg] =                                          \
            make_uint4(cvt2(rb[0], rb[1]), cvt2(rb[2], rb[3]),                 \
                       cvt2(rb[4], rb[5]), cvt2(rb[6], rb[7]));                \
        *(uint4*)&sB[buf][ar][aseg + 8] =                                      \
            make_uint4(cvt2(rb[8], rb[9]),  cvt2(rb[10], rb[11]),              \
                       cvt2(rb[12], rb[13]), cvt2(rb[14], rb[15]));            \
    } while (0)

    const int wm = (wid & 1) * 64;
    const int wn = (wid >> 1) * 32;
    float c[4][4][4];
#pragma unroll
    for (int i = 0; i < 4; i++)
#pragma unroll
        for (int j = 0; j < 4; j++)
#pragma unroll
            for (int q = 0; q < 4; q++) c[i][j][q] = 0.f;

    const int aLdRow = lane & 15;
    const int aLdCol = (lane >> 4) * 8;
    const int bLdRow = ((lane >> 4) << 3) + (lane & 7);
    const int bLdCol = lane & 8;

#define MMA_STAGE(buf)                                                        \
    do {                                                                      \
        _Pragma("unroll")                                                     \
        for (int kf = 0; kf < 2; kf++) {                                      \
            uint32_t AF[4][4], BF[2][4];                                      \
            _Pragma("unroll")                                                 \
            for (int mf = 0; mf < 4; mf++)                                    \
                ldsm_x4(AF[mf][0], AF[mf][1], AF[mf][2], AF[mf][3],           \
                        &sA[buf][wm + mf*16 + aLdRow][kf*16 + aLdCol]);       \
            _Pragma("unroll")                                                 \
            for (int g = 0; g < 2; g++)                                       \
                ldsm_x4(BF[g][0], BF[g][1], BF[g][2], BF[g][3],               \
                        &sB[buf][wn + g*16 + bLdRow][kf*16 + bLdCol]);        \
            _Pragma("unroll")                                                 \
            for (int mf = 0; mf < 4; mf++)                                    \
                _Pragma("unroll")                                             \
                for (int nf = 0; nf < 4; nf++)                                \
                    mma16816(c[mf][nf], AF[mf],                               \
                             BF[nf >> 1][(nf & 1) * 2],                       \
                             BF[nf >> 1][(nf & 1) * 2 + 1]);                  \
        }                                                                     \
    } while (0)

    LOADREGS(0);
    CVTSTS(0);

    int b = 0;
#pragma unroll 1
    for (int kc = 0; kc < NC; kc++) {
        if (kc + 1 < NC) LOADREGS(kc + 1);
        __syncthreads();
        MMA_STAGE(b);
        if (kc + 1 < NC) CVTSTS(b ^ 1);
        b ^= 1;
    }
#undef LOADREGS
#undef CVTSTS
#undef MMA_STAGE

#pragma unroll
    for (int mf = 0; mf < 4; mf++) {
#pragma unroll
        for (int nf = 0; nf < 4; nf++) {
            int r0 = wm + mf * 16 + (lane >> 2);
            int col = n0 + wn + nf * 8 + 2 * (lane & 3);
            if (r0 < rem)
                *(float2*)(out + (size_t)sPos[r0] * IN_F + col) =
                    make_float2(c[mf][nf][0], c[mf][nf][1]);
            if (r0 + 8 < rem)
                *(float2*)(out + (size_t)sPos[r0 + 8] * IN_F + col) =
                    make_float2(c[mf][nf][2], c[mf][nf][3]);
        }
    }
}

// ---------------------------------------------------------------------------
extern "C" void kernel_launch(void* const* d_in, const int* in_sizes, int n_in,
                              void* d_out, int out_size) {
    const int*   tokens   = (const int*)d_in[0];
    const float* head_emb = (const float*)d_in[1];
    const float* t0e      = (const float*)d_in[2];
    const float* t0w      = (const float*)d_in[3];
    const float* t1e      = (const float*)d_in[4];
    const float* t1w      = (const float*)d_in[5];
    float* out = (float*)d_out;
    int n = in_sizes[0];
    if (n > NTOK_MAX) n = NTOK_MAX;

    const __half* B0 = (const __half*)(out + (size_t)CUTROW2 * IN_F);
    const __half* B1 = B0 + (size_t)1024 * 512;

    const int smem0 = (64 * (512 + 8) + 2 * 128 * 72) * (int)sizeof(__half); // 103424
    const int smem1 = (64 * (256 + 8) + 2 * 128 * 72) * (int)sizeof(__half); // 70656
    cudaFuncSetAttribute(dense2_k<512, 0>,
                         cudaFuncAttributeMaxDynamicSharedMemorySize, smem0);
    cudaFuncSetAttribute(dense2_k<256, 1>,
                         cudaFuncAttributeMaxDynamicSharedMemorySize, smem1);

    init_k<<<1, 32>>>();
    classify4_k<<<(n + 255) / 256, 256>>>(tokens, n);
    packA_k<512, CUT1, 0><<<NTOK_MAX / 8, 256>>>(t0e, tokens, out);
    packA_k<256, CUT2, 1><<<NTOK_MAX / 16, 256>>>(t1e, tokens, out);
    packB_k<<<192, 256>>>(t0w, t1w, out);

    dense2_k<512, 0><<<NTOK_MAX / 64, 256, smem0>>>(B0, out);
    dense2_k<256, 1><<<NTOK_MAX / 64, 256, smem1>>>(B1, out);

    head_lo_k<<<CUTROW2, 128>>>(tokens, head_emb, out);
    head_hi_k<<<NTOK_MAX - CUTROW2, 128>>>(tokens, head_emb, out, n);
    fused_hi_k<512, CUT1, 0><<<dim3(3, IN_F / 128), 256>>>(t0e, t0w, tokens, out);
    fused_hi_k<256, CUT2, 1><<<dim3(3, IN_F / 128), 256>>>(t1e, t1w, tokens, out);
}

// round 12
// speedup vs baseline: 1.2089x; 1.2089x over previous
#include <cuda_runtime.h>
#include <cuda_fp16.h>
#include <cstdint>

#define NTOK_MAX (8 * 4096)
#define IN_F 1024
#define CUT1 5000
#define CUT2 20000

// B' scratch: last 384 output rows (B0: 1024x512 halves, B1: 1024x256).
// A' fp16 lives IN-PLACE at the END of each token's own out row:
//   K=512 -> halves [1536,2048), K=256 -> halves [1792,2048).
#define CUTROW2 (NTOK_MAX - 384)

__device__ int g_cnt4[4];   // {t0_lo, t0_hi, t1_lo, t1_hi}
__device__ int g_l0[NTOK_MAX];
__device__ int g_l1[NTOK_MAX];
__device__ int g_h0[NTOK_MAX];
__device__ int g_h1[NTOK_MAX];

// ---------------------------------------------------------------------------
__global__ void init_k() {
    if (threadIdx.x < 4) g_cnt4[threadIdx.x] = 0;
}

__global__ void classify4_k(const int* __restrict__ tokens, int n) {
    int i = blockIdx.x * blockDim.x + threadIdx.x;
    int t = (i < n) ? tokens[i] : -1;
    int c = (t >= CUT2) ? 1 : ((t >= CUT1) ? 0 : -1);
    int hh = (i >= CUTROW2) ? 1 : 0;
    int lane = threadIdx.x & 31;
#pragma unroll
    for (int cc = 0; cc < 2; ++cc) {
#pragma unroll
        for (int h2 = 0; h2 < 2; ++h2) {
            unsigned m = __ballot_sync(0xffffffffu, c == cc && hh == h2);
            if (c == cc && hh == h2) {
                int leader = __ffs(m) - 1;
                int base = 0;
                if (lane == leader) base = atomicAdd(&g_cnt4[cc * 2 + h2], __popc(m));
                base = __shfl_sync(m, base, leader);
                int slot = base + __popc(m & ((1u << lane) - 1u));
                int* lst = h2 ? (cc ? g_h1 : g_h0) : (cc ? g_l1 : g_l0);
                lst[slot] = i;
            }
        }
    }
}

__global__ void head_lo_k(const int* __restrict__ tokens,
                          const float* __restrict__ head_emb,
                          float* __restrict__ out) {
    int p = blockIdx.x;                      // < CUTROW2 by grid
    int t = __ldg(&tokens[p]);
    if (t >= CUT1) return;
    const float4* src = (const float4*)(head_emb + (size_t)t * IN_F);
    float4* dst = (float4*)(out + (size_t)p * IN_F);
    dst[threadIdx.x]       = src[threadIdx.x];
    dst[threadIdx.x + 128] = src[threadIdx.x + 128];
}

__global__ void head_hi_k(const int* __restrict__ tokens,
                          const float* __restrict__ head_emb,
                          float* __restrict__ out, int n) {
    int p = CUTROW2 + blockIdx.x;
    if (p >= n) return;
    int t = __ldg(&tokens[p]);
    if (t >= CUT1) return;
    const float4* src = (const float4*)(head_emb + (size_t)t * IN_F);
    float4* dst = (float4*)(out + (size_t)p * IN_F);
    dst[threadIdx.x]       = src[threadIdx.x];
    dst[threadIdx.x + 128] = src[threadIdx.x + 128];
}

// ---------------------------------------------------------------------------
__device__ __forceinline__ uint32_t cvt2(float f0, float f1) {
    uint32_t r;
    asm("cvt.rn.f16x2.f32 %0, %1, %2;" : "=r"(r) : "f"(f1), "f"(f0));
    return r;
}

// Gather + convert lo-list rows to fp16 A' at the END of each out row.
template <int K, int LOW, int C>
__global__ void packA_k(const float* __restrict__ emb,
                        const int* __restrict__ tokens,
                        float* __restrict__ out) {
    constexpr int TPR = K / 16;
    constexpr int RPB = 256 / TPR;
    constexpr int AOFF = 2048 - K;         // halves offset within row
    __shared__ int sIdx[RPB];
    const int cnt = g_cnt4[C * 2];
    const int r0 = blockIdx.x * RPB;
    if (r0 >= cnt) return;
    if (threadIdx.x < RPB) {
        int rr = r0 + threadIdx.x;
        sIdx[threadIdx.x] = (rr < cnt) ? (C ? g_l1 : g_l0)[rr] : 0;
    }
    __syncthreads();
    int r = r0 + threadIdx.x / TPR;
    if (r >= cnt) return;
    int pos = sIdx[threadIdx.x / TPR];
    int j = (threadIdx.x % TPR) * 16;
    int tok = __ldg(&tokens[pos]) - LOW;
    const float4* src = (const float4*)(emb + (size_t)tok * K + j);
    float4 v0 = src[0], v1 = src[1], v2 = src[2], v3 = src[3];
    uint4 o0 = make_uint4(cvt2(v0.x, v0.y), cvt2(v0.z, v0.w),
                          cvt2(v1.x, v1.y), cvt2(v1.z, v1.w));
    uint4 o1 = make_uint4(cvt2(v2.x, v2.y), cvt2(v2.z, v2.w),
                          cvt2(v3.x, v3.y), cvt2(v3.z, v3.w));
    __half* dst = (__half*)(out + (size_t)pos * IN_F) + AOFF + j;
    *(uint4*)dst = o0;
    *(uint4*)(dst + 8) = o1;
}

// Convert both weight matrices into fp16 B' scratch (tail 384 rows of out).
__global__ void packB_k(const float* __restrict__ w0,
                        const float* __restrict__ w1,
                        float* __restrict__ out) {
    __half* B0 = (__half*)(out + (size_t)CUTROW2 * IN_F);
    __half* B1 = B0 + (size_t)1024 * 512;
    int K, r, j;
    const float* w;
    __half* Bp;
    if (blockIdx.x < 128) {
        K = 512; w = w0; Bp = B0;
        r = blockIdx.x * 8 + threadIdx.x / 32;
        j = (threadIdx.x % 32) * 16;
    } else {
        K = 256; w = w1; Bp = B1;
        r = (blockIdx.x - 128) * 16 + threadIdx.x / 16;
        j = (threadIdx.x % 16) * 16;
    }
    const float4* src = (const float4*)(w + (size_t)r * K + j);
    float4 v0 = src[0], v1 = src[1], v2 = src[2], v3 = src[3];
    uint4 o0 = make_uint4(cvt2(v0.x, v0.y), cvt2(v0.z, v0.w),
                          cvt2(v1.x, v1.y), cvt2(v1.z, v1.w));
    uint4 o1 = make_uint4(cvt2(v2.x, v2.y), cvt2(v2.z, v2.w),
                          cvt2(v3.x, v3.y), cvt2(v3.z, v3.w));
    __half* dst = Bp + (size_t)r * K + j;
    *(uint4*)dst = o0;
    *(uint4*)(dst + 8) = o1;
}

// ---------------------------------------------------------------------------
__device__ __forceinline__ void ldsm_x4(uint32_t& r0, uint32_t& r1,
                                        uint32_t& r2, uint32_t& r3,
                                        const void* smem_ptr) {
    uint32_t addr = (uint32_t)__cvta_generic_to_shared(smem_ptr);
    asm volatile("ldmatrix.sync.aligned.m8n8.x4.shared.b16 {%0,%1,%2,%3}, [%4];"
                 : "=r"(r0), "=r"(r1), "=r"(r2), "=r"(r3) : "r"(addr));
}

__device__ __forceinline__ void mma16816(float* c, const uint32_t* a,
                                         uint32_t b0, uint32_t b1) {
    asm volatile(
        "mma.sync.aligned.m16n8k16.row.col.f32.f16.f16.f32 "
        "{%0,%1,%2,%3}, {%4,%5,%6,%7}, {%8,%9}, {%0,%1,%2,%3};"
        : "+f"(c[0]), "+f"(c[1]), "+f"(c[2]), "+f"(c[3])
        : "r"(a[0]), "r"(a[1]), "r"(a[2]), "r"(a[3]), "r"(b0), "r"(b1));
}

__device__ __forceinline__ void cp16(void* dst_smem, const void* src) {
    uint32_t d = (uint32_t)__cvta_generic_to_shared(dst_smem);
    asm volatile("cp.async.cg.shared.global [%0], [%1], 16;\n" :: "r"(d), "l"(src));
}

// ---------------------------------------------------------------------------
// Dense pass 1: 128x128 tiles, 3-stage cp.async. A' read in place (row end);
// computes columns [0, NSLICES*128) which never overlap A'.
template <int K, int C>
__global__ void __launch_bounds__(256, 2)
dense1_k(const __half* __restrict__ Bp, float* __restrict__ out) {
    constexpr int TM = 128, TN = 128, TKH = 64, LD = 72;
    constexpr int NC = K / TKH;
    constexpr int AOFF = 2048 - K;
    extern __shared__ __half dsm[];
    __half* As = dsm;                       // [3][TM][LD]
    __half* Bs = dsm + 3 * TM * LD;         // [3][TN][LD]
    __shared__ int sPos[TM];

    const int count = g_cnt4[C * 2];
    const int rowBase = blockIdx.x * TM;
    if (rowBase >= count) return;
    const int rem = min(TM, count - rowBase);
    const int n0 = blockIdx.y * TN;
    const int tid = threadIdx.x;
    const int lane = tid & 31;
    const int wid = tid >> 5;
    const int* idxList = C ? g_l1 : g_l0;

    if (tid < TM) sPos[tid] = idxList[rowBase + min(tid, rem - 1)];

    // loaders: 2 threads/row, 32 halves each
    const int lr = tid >> 1;
    const int off = (tid & 1) * 32;
    const int myPos = idxList[rowBase + min(lr, rem - 1)];
    const __half* aP = (const __half*)(out + (size_t)myPos * IN_F) + AOFF + off;
    const __half* bP = Bp + (size_t)(n0 + lr) * K + off;

#define DISSUE(s, kc)                                                     \
    do {                                                                  \
        const __half* ap_ = aP + (kc) * TKH;                              \
        const __half* bp_ = bP + (kc) * TKH;                              \
        _Pragma("unroll")                                                 \
        for (int q_ = 0; q_ < 4; q_++) {                                  \
            cp16(&As[((s) * TM + lr) * LD + off + q_ * 8], ap_ + q_ * 8); \
            cp16(&Bs[((s) * TN + lr) * LD + off + q_ * 8], bp_ + q_ * 8); \
        }                                                                 \
    } while (0)

    DISSUE(0, 0);
    asm volatile("cp.async.commit_group;\n");
    DISSUE(1, 1);
    asm volatile("cp.async.commit_group;\n");

    const int wm = (wid & 1) * 64;
    const int wn = (wid >> 1) * 32;
    float c[4][4][4];
#pragma unroll
    for (int i = 0; i < 4; i++)
#pragma unroll
        for (int j = 0; j < 4; j++)
#pragma unroll
            for (int q = 0; q < 4; q++) c[i][j][q] = 0.f;

    const int aLdRow = lane & 15;
    const int aLdCol = (lane >> 4) * 8;
    const int bLdRow = ((lane >> 4) << 3) + (lane & 7);
    const int bLdCol = lane & 8;

    int s = 0;
#pragma unroll 1
    for (int kc = 0; kc < NC; kc++) {
        asm volatile("cp.async.wait_group 1;\n");
        __syncthreads();
        if (kc + 2 < NC) {
            int sn = (s + 2 >= 3) ? s - 1 : s + 2;
            DISSUE(sn, kc + 2);
        }
        asm volatile("cp.async.commit_group;\n");

        const __half* ab = As + s * TM * LD;
        const __half* bb = Bs + s * TN * LD;
#pragma unroll
        for (int kf = 0; kf < 4; kf++) {
            uint32_t AF[4][4], BF[2][4];
#pragma unroll
            for (int mf = 0; mf < 4; mf++)
                ldsm_x4(AF[mf][0], AF[mf][1], AF[mf][2], AF[mf][3],
                        ab + (wm + mf * 16 + aLdRow) * LD + kf * 16 + aLdCol);
#pragma unroll
            for (int g = 0; g < 2; g++)
                ldsm_x4(BF[g][0], BF[g][1], BF[g][2], BF[g][3],
                        bb + (wn + g * 16 + bLdRow) * LD + kf * 16 + bLdCol);
#pragma unroll
            for (int mf = 0; mf < 4; mf++)
#pragma unroll
                for (int nf = 0; nf < 4; nf++)
                    mma16816(c[mf][nf], AF[mf],
                             BF[nf >> 1][(nf & 1) * 2], BF[nf >> 1][(nf & 1) * 2 + 1]);
        }
        s = (s == 2) ? 0 : s + 1;
    }
#undef DISSUE

#pragma unroll
    for (int mf = 0; mf < 4; mf++) {
#pragma unroll
        for (int nf = 0; nf < 4; nf++) {
            int r0 = wm + mf * 16 + (lane >> 2);
            int col = n0 + wn + nf * 8 + 2 * (lane & 3);
            if (r0 < rem)
                *(float2*)(out + (size_t)sPos[r0] * IN_F + col) =
                    make_float2(c[mf][nf][0], c[mf][nf][1]);
            if (r0 + 8 < rem)
                *(float2*)(out + (size_t)sPos[r0 + 8] * IN_F + col) =
                    make_float2(c[mf][nf][2], c[mf][nf][3]);
        }
    }
}

// ---------------------------------------------------------------------------
// Dense pass 2: 64-row CTAs own their rows exclusively. A' -> smem first,
// then compute ONLY the N-slices overlapping the in-place A' region and
// overwrite them. S0 = first slice, NS = slice count.
template <int K, int C, int S0, int NS>
__global__ void __launch_bounds__(256, 2)
dense2_k(const __half* __restrict__ Bp, float* __restrict__ out) {
    constexpr int LDA = K + 8;
    constexpr int LDB = 72;
    constexpr int NCK = K / 64;
    constexpr int G = NS * NCK;
    constexpr int AOFF = 2048 - K;
    extern __shared__ __half dsm[];
    __half* Asm = dsm;                     // [64][LDA]
    __half* Bsm = dsm + 64 * LDA;          // [2][128][LDB]
    __shared__ int sPos[64];

    const int count = g_cnt4[C * 2];
    const int rowBase = blockIdx.x * 64;
    if (rowBase >= count) return;
    const int rem = min(64, count - rowBase);
    const int tid = threadIdx.x;
    const int lane = tid & 31;
    const int wid = tid >> 5;

    if (tid < 64) sPos[tid] = (C ? g_l1 : g_l0)[rowBase + min(tid, rem - 1)];
    __syncthreads();

    // A load: 4 threads per row
    {
        int row = tid >> 2;
        const __half* aRow = (const __half*)(out + (size_t)sPos[row] * IN_F) + AOFF;
#pragma unroll
        for (int q = 0; q < K / 32; q++) {
            int col = ((tid & 3) + q * 4) * 8;
            cp16(&Asm[row * LDA + col], aRow + col);
        }
    }

    const int brow = tid >> 1;
#define BISSUE(g)                                                         \
    do {                                                                  \
        int s0_ = S0 + (g) / NCK, kc_ = (g) % NCK, stg_ = (g) & 1;        \
        const __half* bsrc = Bp + (size_t)(s0_ * 128 + brow) * K          \
                             + kc_ * 64;                                  \
        __half* bdst = Bsm + stg_ * (128 * LDB) + brow * LDB;             \
        _Pragma("unroll")                                                 \
        for (int p_ = 0; p_ < 4; p_++) {                                  \
            int col = ((tid & 1) + p_ * 2) * 8;                           \
            cp16(bdst + col, bsrc + col);                                 \
        }                                                                 \
    } while (0)

    BISSUE(0);
    asm volatile("cp.async.commit_group;\n");

    const int wm = (wid & 1) * 32;
    const int wn = (wid >> 1) * 32;
    float c[2][4][4];
#pragma unroll
    for (int i = 0; i < 2; i++)
#pragma unroll
        for (int j = 0; j < 4; j++)
#pragma unroll
            for (int q = 0; q < 4; q++) c[i][j][q] = 0.f;

    const int aLdRow = lane & 15;
    const int aLdCol = (lane >> 4) * 8;
    const int bLdRow = ((lane >> 4) << 3) + (lane & 7);
    const int bLdCol = lane & 8;

#pragma unroll 1
    for (int g = 0; g < G; g++) {
        asm volatile("cp.async.wait_group 0;\n");
        __syncthreads();
        if (g + 1 < G) {
            BISSUE(g + 1);
            asm volatile("cp.async.commit_group;\n");
        }
        const int s0 = S0 + g / NCK, kc = g % NCK, stg = g & 1;
        const __half* bb = Bsm + stg * (128 * LDB);
#pragma unroll
        for (int kf = 0; kf < 4; kf++) {
            uint32_t AF[2][4], BF[2][4];
#pragma unroll
            for (int mf = 0; mf < 2; mf++)
                ldsm_x4(AF[mf][0], AF[mf][1], AF[mf][2], AF[mf][3],
                        &Asm[(wm + mf * 16 + aLdRow) * LDA
                             + kc * 64 + kf * 16 + aLdCol]);
#pragma unroll
            for (int gg = 0; gg < 2; gg++)
                ldsm_x4(BF[gg][0], BF[gg][1], BF[gg][2], BF[gg][3],
                        bb + (wn + gg * 16 + bLdRow) * LDB + kf * 16 + bLdCol);
#pragma unroll
            for (int mf = 0; mf < 2; mf++)
#pragma unroll
                for (int nf = 0; nf < 4; nf++)
                    mma16816(c[mf][nf], AF[mf],
                             BF[nf >> 1][(nf & 1) * 2], BF[nf >> 1][(nf & 1) * 2 + 1]);
        }

        if (kc == NCK - 1) {
            int n0 = s0 * 128;
#pragma unroll
            for (int mf = 0; mf < 2; mf++) {
#pragma unroll
                for (int nf = 0; nf < 4; nf++) {
                    int r0 = wm + mf * 16 + (lane >> 2);
                    int col = n0 + wn + nf * 8 + 2 * (lane & 3);
                    if (r0 < rem)
                        *(float2*)(out + (size_t)sPos[r0] * IN_F + col) =
                            make_float2(c[mf][nf][0], c[mf][nf][1]);
                    if (r0 + 8 < rem)
                        *(float2*)(out + (size_t)sPos[r0 + 8] * IN_F + col) =
                            make_float2(c[mf][nf][2], c[mf][nf][3]);
#pragma unroll
                    for (int q = 0; q < 4; q++) c[mf][nf][q] = 0.f;
                }
            }
        }
    }
#undef BISSUE
}

// ---------------------------------------------------------------------------
// Fused gather+convert fp16 GEMM for the <=384+overflow hi-list rows.
template <int K, int LOW, int C>
__global__ void __launch_bounds__(256, 2)
fused_hi_k(const float* __restrict__ emb,
           const float* __restrict__ w,
           const int* __restrict__ tokens,
           float* __restrict__ out) {
    constexpr int TM = 128, TN = 128, LD = 40;
    constexpr int NC = K / 32;
    __shared__ __align__(16) __half sA[2][TM][LD];
    __shared__ __align__(16) __half sB[2][TN][LD];
    __shared__ int sPos[TM];

    const int count = g_cnt4[C * 2 + 1];
    const int rowBase = blockIdx.x * TM;
    if (rowBase >= count) return;
    const int rem = min(TM, count - rowBase);
    const int n0 = blockIdx.y * TN;
    const int tid = threadIdx.x;
    const int lane = tid & 31;
    const int wid = tid >> 5;

    if (tid < TM) sPos[tid] = (C ? g_h1 : g_h0)[rowBase + min(tid, rem - 1)];
    __syncthreads();

    const int ar = tid >> 1;
    const int aseg = (tid & 1) * 16;
    const float* aPtr = emb + (size_t)(__ldg(&tokens[sPos[ar]]) - LOW) * K + aseg;
    const float* bPtr = w + (size_t)(n0 + ar) * K + aseg;

    float ra[16], rb[16];
#define LOADREGS(kc)                                              \
    do {                                                          \
        const float* ap_ = aPtr + (kc) * 32;                      \
        const float* bp_ = bPtr + (kc) * 32;                      \
        _Pragma("unroll")                                         \
        for (int q_ = 0; q_ < 4; q_++) {                          \
            float4 va_ = *(const float4*)(ap_ + q_ * 4);          \
            float4 vb_ = *(const float4*)(bp_ + q_ * 4);          \
            ra[q_*4+0]=va_.x; ra[q_*4+1]=va_.y;                   \
            ra[q_*4+2]=va_.z; ra[q_*4+3]=va_.w;                   \
            rb[q_*4+0]=vb_.x; rb[q_*4+1]=vb_.y;                   \
            rb[q_*4+2]=vb_.z; rb[q_*4+3]=vb_.w;                   \
        }                                                         \
    } while (0)

#define CVTSTS(buf)                                                            \
    do {                                                                       \
        *(uint4*)&sA[buf][ar][aseg] =                                          \
            make_uint4(cvt2(ra[0], ra[1]), cvt2(ra[2], ra[3]),                 \
                       cvt2(ra[4], ra[5]), cvt2(ra[6], ra[7]));                \
        *(uint4*)&sA[buf][ar][aseg + 8] =                                      \
            make_uint4(cvt2(ra[8], ra[9]),  cvt2(ra[10], ra[11]),              \
                       cvt2(ra[12], ra[13]), cvt2(ra[14], ra[15]));            \
        *(uint4*)&sB[buf][ar][aseg] =                                          \
            make_uint4(cvt2(rb[0], rb[1]), cvt2(rb[2], rb[3]),                 \
                       cvt2(rb[4], rb[5]), cvt2(rb[6], rb[7]));                \
        *(uint4*)&sB[buf][ar][aseg + 8] =                                      \
            make_uint4(cvt2(rb[8], rb[9]),  cvt2(rb[10], rb[11]),              \
                       cvt2(rb[12], rb[13]), cvt2(rb[14], rb[15]));            \
    } while (0)

    const int wm = (wid & 1) * 64;
    const int wn = (wid >> 1) * 32;
    float c[4][4][4];
#pragma unroll
    for (int i = 0; i < 4; i++)
#pragma unroll
        for (int j = 0; j < 4; j++)
#pragma unroll
            for (int q = 0; q < 4; q++) c[i][j][q] = 0.f;

    const int aLdRow = lane & 15;
    const int aLdCol = (lane >> 4) * 8;
    const int bLdRow = ((lane >> 4) << 3) + (lane & 7);
    const int bLdCol = lane & 8;

#define MMA_STAGE(buf)                                                        \
    do {                                                                      \
        _Pragma("unroll")                                                     \
        for (int kf = 0; kf < 2; kf++) {                                      \
            uint32_t AF[4][4], BF[2][4];                                      \
            _Pragma("unroll")                                                 \
            for (int mf = 0; mf < 4; mf++)                                    \
                ldsm_x4(AF[mf][0], AF[mf][1], AF[mf][2], AF[mf][3],           \
                        &sA[buf][wm + mf*16 + aLdRow][kf*16 + aLdCol]);       \
            _Pragma("unroll")                                                 \
            for (int g = 0; g < 2; g++)                                       \
                ldsm_x4(BF[g][0], BF[g][1], BF[g][2], BF[g][3],               \
                        &sB[buf][wn + g*16 + bLdRow][kf*16 + bLdCol]);        \
            _Pragma("unroll")                                                 \
            for (int mf = 0; mf < 4; mf++)                                    \
                _Pragma("unroll")                                             \
                for (int nf = 0; nf < 4; nf++)                                \
                    mma16816(c[mf][nf], AF[mf],                               \
                             BF[nf >> 1][(nf & 1) * 2],                       \
                             BF[nf >> 1][(nf & 1) * 2 + 1]);                  \
        }                                                                     \
    } while (0)

    LOADREGS(0);
    CVTSTS(0);

    int b = 0;
#pragma unroll 1
    for (int kc = 0; kc < NC; kc++) {
        if (kc + 1 < NC) LOADREGS(kc + 1);
        __syncthreads();
        MMA_STAGE(b);
        if (kc + 1 < NC) CVTSTS(b ^ 1);
        b ^= 1;
    }
#undef LOADREGS
#undef CVTSTS
#undef MMA_STAGE

#pragma unroll
    for (int mf = 0; mf < 4; mf++) {
#pragma unroll
        for (int nf = 0; nf < 4; nf++) {
            int r0 = wm + mf * 16 + (lane >> 2);
            int col = n0 + wn + nf * 8 + 2 * (lane & 3);
            if (r0 < rem)
                *(float2*)(out + (size_t)sPos[r0] * IN_F + col) =
                    make_float2(c[mf][nf][0], c[mf][nf][1]);
            if (r0 + 8 < rem)
                *(float2*)(out + (size_t)sPos[r0 + 8] * IN_F + col) =
                    make_float2(c[mf][nf][2], c[mf][nf][3]);
        }
    }
}

// ---------------------------------------------------------------------------
extern "C" void kernel_launch(void* const* d_in, const int* in_sizes, int n_in,
                              void* d_out, int out_size) {
    const int*   tokens   = (const int*)d_in[0];
    const float* head_emb = (const float*)d_in[1];
    const float* t0e      = (const float*)d_in[2];
    const float* t0w      = (const float*)d_in[3];
    const float* t1e      = (const float*)d_in[4];
    const float* t1w      = (const float*)d_in[5];
    float* out = (float*)d_out;
    int n = in_sizes[0];
    if (n > NTOK_MAX) n = NTOK_MAX;

    const __half* B0 = (const __half*)(out + (size_t)CUTROW2 * IN_F);
    const __half* B1 = B0 + (size_t)1024 * 512;

    const int d1Smem = 3 * (128 + 128) * 72 * (int)sizeof(__half);           // 110592
    const int d2Smem0 = (64 * 520 + 2 * 128 * 72) * (int)sizeof(__half);     // 103424
    const int d2Smem1 = (64 * 264 + 2 * 128 * 72) * (int)sizeof(__half);     // 70656
    cudaFuncSetAttribute(dense1_k<512, 0>,
                         cudaFuncAttributeMaxDynamicSharedMemorySize, d1Smem);
    cudaFuncSetAttribute(dense1_k<256, 1>,
                         cudaFuncAttributeMaxDynamicSharedMemorySize, d1Smem);
    cudaFuncSetAttribute(dense2_k<512, 0, 6, 2>,
                         cudaFuncAttributeMaxDynamicSharedMemorySize, d2Smem0);
    cudaFuncSetAttribute(dense2_k<256, 1, 7, 1>,
                         cudaFuncAttributeMaxDynamicSharedMemorySize, d2Smem1);

    init_k<<<1, 32>>>();
    classify4_k<<<(n + 255) / 256, 256>>>(tokens, n);
    packA_k<512, CUT1, 0><<<NTOK_MAX / 8, 256>>>(t0e, tokens, out);
    packA_k<256, CUT2, 1><<<NTOK_MAX / 16, 256>>>(t1e, tokens, out);
    packB_k<<<192, 256>>>(t0w, t1w, out);

    // pass 1: columns that never overlap in-place A'
    dense1_k<512, 0><<<dim3(NTOK_MAX / 128, 6), 256, d1Smem>>>(B0, out);
    dense1_k<256, 1><<<dim3(NTOK_MAX / 128, 7), 256, d1Smem>>>(B1, out);
    // pass 2: A'-overlap columns, row-exclusive CTAs (A' smem-staged first)
    dense2_k<512, 0, 6, 2><<<NTOK_MAX / 64, 256, d2Smem0>>>(B0, out);
    dense2_k<256, 1, 7, 1><<<NTOK_MAX / 64, 256, d2Smem1>>>(B1, out);

    head_lo_k<<<CUTROW2, 128>>>(tokens, head_emb, out);
    head_hi_k<<<NTOK_MAX - CUTROW2, 128>>>(tokens, head_emb, out, n);
    fused_hi_k<512, CUT1, 0><<<dim3(3, IN_F / 128), 256>>>(t0e, t0w, tokens, out);
    fused_hi_k<256, CUT2, 1><<<dim3(3, IN_F / 128), 256>>>(t1e, t1w, tokens, out);
}